// round 1
// baseline (speedup 1.0000x reference)
#include <cuda_runtime.h>
#include <math.h>

#define NB 8
#define NC 32
#define NR 2048
#define NI 64
#define NO 64

// Scratch (static device globals — no allocation in kernel_launch)
__device__ float g_priors[NB * NC * NR * NO];   // 134 MB, layout [b][c][r][o]
__device__ float g_s[NB * NC * NO];             // s per iteration
__device__ float g_w[NB * NC * NO];             // cumulative v (softmax weight factor)

// ---------------------------------------------------------------------------
// Kernel 1: priors[b,c,r,o] = sum_i x[b,c,r,i] * W[c,r,i,o]
// Block: 128 threads, handles (c, 8 consecutive r). Thread (rj = t/16, og = t%16)
// computes 8 batches x 4 outputs (o = 4*og .. 4*og+3) for one r.
// W read exactly once from HBM (float4, coalesced). x staged via smem.
// Block (0,0) also zeroes g_w (idempotent, safe across block ordering).
// ---------------------------------------------------------------------------
__global__ __launch_bounds__(128) void priors_kernel(
    const float* __restrict__ x, const float* __restrict__ Wt)
{
    const int c  = blockIdx.y;
    const int r0 = blockIdx.x * 8;
    const int t  = threadIdx.x;

    if (blockIdx.x == 0 && blockIdx.y == 0) {
        for (int q = t; q < NB * NC * NO; q += 128) g_w[q] = 0.0f;
    }

    __shared__ float sX[NB * 8 * NI];   // [b][rj][i], 16 KB
    {
        const float4* x4 = (const float4*)x;
        float4* sX4 = (float4*)sX;
#pragma unroll
        for (int q = 0; q < 8; q++) {
            int idx = t + 128 * q;          // 0..1023 float4s
            int b   = idx >> 7;
            int rem = idx & 127;
            int rj  = rem >> 4;
            int f   = rem & 15;
            sX4[(b * 8 + rj) * 16 + f] =
                x4[((size_t)((b * NC + c) * NR + r0 + rj)) * 16 + f];
        }
    }
    __syncthreads();

    const int rj = t >> 4;
    const int og = t & 15;
    const int r  = r0 + rj;
    const float4* w4p = (const float4*)(Wt + (size_t)(c * NR + r) * (NI * NO));

    float4 acc[NB];
#pragma unroll
    for (int b = 0; b < NB; b++) acc[b] = make_float4(0.f, 0.f, 0.f, 0.f);

#pragma unroll 4
    for (int i = 0; i < NI; i++) {
        float4 w = w4p[i * 16 + og];
#pragma unroll
        for (int b = 0; b < NB; b++) {
            float xv = sX[(b * 8 + rj) * NI + i];
            acc[b].x += xv * w.x;
            acc[b].y += xv * w.y;
            acc[b].z += xv * w.z;
            acc[b].w += xv * w.w;
        }
    }

#pragma unroll
    for (int b = 0; b < NB; b++) {
        ((float4*)g_priors)[(size_t)((b * NC + c) * NR + r) * 16 + og] = acc[b];
    }
}

// ---------------------------------------------------------------------------
// Kernel 2: one routing iteration.
// For each (b,c,o): l_r = priors[b,c,r,o] * w[b,c,o];
//   s[b,c,o] = sum_r softmax_r(l) * priors = (sum e^l * p) / (sum e^l)
// Online softmax, 4 independent chains per thread (float4 over o).
// Block per (b,c): 512 threads; g = t/16 (32 r-lanes), o4 = t%16.
// ---------------------------------------------------------------------------
#define ONLINE(p, wv, m, d, n)                                        \
    do {                                                              \
        float l_ = (p) * (wv);                                        \
        if (l_ <= (m)) {                                              \
            float e_ = __expf(l_ - (m));                              \
            (d) += e_;                                                \
            (n) += (p) * e_;                                          \
        } else {                                                      \
            float f_ = __expf((m) - l_);                              \
            (d) = (d) * f_ + 1.0f;                                    \
            (n) = (n) * f_ + (p);                                     \
            (m) = l_;                                                 \
        }                                                             \
    } while (0)

__global__ __launch_bounds__(512) void iter_kernel()
{
    const int bc = blockIdx.x;          // b*NC + c
    const int t  = threadIdx.x;
    const int o4 = t & 15;
    const int g  = t >> 4;              // 0..31

    const float4* p4 = (const float4*)(g_priors + (size_t)bc * NR * NO);
    const float4 wv  = ((const float4*)g_w)[bc * 16 + o4];

    float m0 = -INFINITY, m1 = -INFINITY, m2 = -INFINITY, m3 = -INFINITY;
    float d0 = 0.f, d1 = 0.f, d2 = 0.f, d3 = 0.f;
    float n0 = 0.f, n1 = 0.f, n2 = 0.f, n3 = 0.f;

#pragma unroll 4
    for (int k = 0; k < NR / 32; k++) {
        float4 p = p4[(size_t)(g + 32 * k) * 16 + o4];
        ONLINE(p.x, wv.x, m0, d0, n0);
        ONLINE(p.y, wv.y, m1, d1, n1);
        ONLINE(p.z, wv.z, m2, d2, n2);
        ONLINE(p.w, wv.w, m3, d3, n3);
    }

    __shared__ float sm[3][32][64];     // m / den / num, 24 KB
    {
        int ob = o4 * 4;
        sm[0][g][ob + 0] = m0; sm[1][g][ob + 0] = d0; sm[2][g][ob + 0] = n0;
        sm[0][g][ob + 1] = m1; sm[1][g][ob + 1] = d1; sm[2][g][ob + 1] = n1;
        sm[0][g][ob + 2] = m2; sm[1][g][ob + 2] = d2; sm[2][g][ob + 2] = n2;
        sm[0][g][ob + 3] = m3; sm[1][g][ob + 3] = d3; sm[2][g][ob + 3] = n3;
    }
    __syncthreads();

    if (t < 64) {
        float M = -INFINITY, D = 0.f, N = 0.f;
#pragma unroll 8
        for (int g2 = 0; g2 < 32; g2++) {
            float mg = sm[0][g2][t];
            float Mn = fmaxf(M, mg);
            float f1 = __expf(M - Mn);
            float f2 = __expf(mg - Mn);
            D = D * f1 + sm[1][g2][t] * f2;
            N = N * f1 + sm[2][g2][t] * f2;
            M = Mn;
        }
        g_s[bc * NO + t] = N / D;
    }
}

// ---------------------------------------------------------------------------
// Kernel 3: squash. n2 = sum(s^2) over the WHOLE tensor (scalar);
// v = (n2/(1+n2)) * s / sqrt(n2) = s * sqrt(n2)/(1+n2).
// If last: write v to out. Else: g_w += v (accumulates logits weight).
// Single block of 512 threads (16384 elements = 4096 float4).
// ---------------------------------------------------------------------------
__global__ __launch_bounds__(512) void squash_kernel(float* __restrict__ out, int last)
{
    const int t = threadIdx.x;
    const float4* s4 = (const float4*)g_s;

    float acc = 0.f;
    float4 sv[8];
#pragma unroll
    for (int q = 0; q < 8; q++) {
        float4 v = s4[t + 512 * q];
        sv[q] = v;
        acc += v.x * v.x + v.y * v.y + v.z * v.z + v.w * v.w;
    }

    __shared__ float red[16];
    __shared__ float s_scale;
#pragma unroll
    for (int off = 16; off > 0; off >>= 1)
        acc += __shfl_xor_sync(0xFFFFFFFFu, acc, off);
    if ((t & 31) == 0) red[t >> 5] = acc;
    __syncthreads();
    if (t < 32) {
        float a = (t < 16) ? red[t] : 0.f;
#pragma unroll
        for (int off = 8; off > 0; off >>= 1)
            a += __shfl_xor_sync(0xFFFFFFFFu, a, off);
        if (t == 0) s_scale = sqrtf(a) / (1.0f + a);
    }
    __syncthreads();
    const float sc = s_scale;

    if (last) {
        float4* o4 = (float4*)out;
#pragma unroll
        for (int q = 0; q < 8; q++) {
            float4 v = sv[q];
            o4[t + 512 * q] = make_float4(v.x * sc, v.y * sc, v.z * sc, v.w * sc);
        }
    } else {
        float4* w4 = (float4*)g_w;
#pragma unroll
        for (int q = 0; q < 8; q++) {
            float4 v = sv[q];
            float4 w = w4[t + 512 * q];
            w.x += v.x * sc; w.y += v.y * sc; w.z += v.z * sc; w.w += v.w * sc;
            w4[t + 512 * q] = w;
        }
    }
}

// ---------------------------------------------------------------------------
extern "C" void kernel_launch(void* const* d_in, const int* in_sizes, int n_in,
                              void* d_out, int out_size)
{
    (void)in_sizes; (void)n_in; (void)out_size;
    const float* x  = (const float*)d_in[0];
    const float* Wt = (const float*)d_in[1];
    float* out = (float*)d_out;

    priors_kernel<<<dim3(NR / 8, NC), 128>>>(x, Wt);

    // iteration 0 (w = 0 -> uniform softmax -> mean)
    iter_kernel<<<NB * NC, 512>>>();
    squash_kernel<<<1, 512>>>(nullptr, 0);      // w = v0

    // iteration 1 (logits = priors * v0)
    iter_kernel<<<NB * NC, 512>>>();
    squash_kernel<<<1, 512>>>(nullptr, 0);      // w = v0 + v1

    // iteration 2 (logits = priors * (v0+v1)); final squash -> output
    iter_kernel<<<NB * NC, 512>>>();
    squash_kernel<<<1, 512>>>(out, 1);
}

// round 2
// speedup vs baseline: 1.1757x; 1.1757x over previous
#include <cuda_runtime.h>
#include <cuda_fp16.h>
#include <math.h>

#define NB 8
#define NC 32
#define NR 2048
#define NI 64
#define NO 64

// Scratch (static device globals — no allocation in kernel_launch)
__device__ __half g_ph[NB * NC * NR * NO];      // 67 MB fp16 priors -> L2 resident
__device__ float  g_w[NB * NC * NO];            // cumulative v (logit weight)
__device__ float  g_pden[2 * NB * NC * NO];     // per-half softmax denominators
__device__ float  g_pnum[2 * NB * NC * NO];     // per-half softmax numerators

// ---------------------------------------------------------------------------
// Kernel 1: priors[b,c,r,o] = sum_i x[b,c,r,i] * W[c,r,i,o], stored as fp16.
// W and x loaded with __ldcs (streaming / evict-first) so the 1.07 GB of W
// does not evict the 67 MB fp16 priors from L2.
// ---------------------------------------------------------------------------
__global__ __launch_bounds__(128) void priors_kernel(
    const float* __restrict__ x, const float* __restrict__ Wt)
{
    const int c  = blockIdx.y;
    const int r0 = blockIdx.x * 8;
    const int t  = threadIdx.x;

    if (blockIdx.x == 0 && blockIdx.y == 0) {
        for (int q = t; q < NB * NC * NO; q += 128) g_w[q] = 0.0f;
    }

    __shared__ float sX[NB * 8 * NI];   // [b][rj][i], 16 KB
    {
        const float4* x4 = (const float4*)x;
        float4* sX4 = (float4*)sX;
#pragma unroll
        for (int q = 0; q < 8; q++) {
            int idx = t + 128 * q;          // 0..1023 float4s
            int b   = idx >> 7;
            int rem = idx & 127;
            int rj  = rem >> 4;
            int f   = rem & 15;
            sX4[(b * 8 + rj) * 16 + f] =
                __ldcs(&x4[((size_t)((b * NC + c) * NR + r0 + rj)) * 16 + f]);
        }
    }
    __syncthreads();

    const int rj = t >> 4;
    const int og = t & 15;
    const int r  = r0 + rj;
    const float4* w4p = (const float4*)(Wt + (size_t)(c * NR + r) * (NI * NO));

    float4 acc[NB];
#pragma unroll
    for (int b = 0; b < NB; b++) acc[b] = make_float4(0.f, 0.f, 0.f, 0.f);

#pragma unroll 4
    for (int i = 0; i < NI; i++) {
        float4 w = __ldcs(&w4p[i * 16 + og]);
#pragma unroll
        for (int b = 0; b < NB; b++) {
            float xv = sX[(b * 8 + rj) * NI + i];
            acc[b].x += xv * w.x;
            acc[b].y += xv * w.y;
            acc[b].z += xv * w.z;
            acc[b].w += xv * w.w;
        }
    }

#pragma unroll
    for (int b = 0; b < NB; b++) {
        union { uint2 u; __half2 h[2]; } pk;
        pk.h[0] = __floats2half2_rn(acc[b].x, acc[b].y);
        pk.h[1] = __floats2half2_rn(acc[b].z, acc[b].w);
        *(uint2*)(g_ph + (size_t)((b * NC + c) * NR + r) * NO + 4 * og) = pk.u;
    }
}

// ---------------------------------------------------------------------------
// Kernel 2: one routing iteration (no max needed: |w|<=2, |p|<=~16 so
// |logit| <= ~32, exp() safe in fp32; max logit over 2048 symmetric samples
// is positive so the denominator is well-conditioned).
// Grid = 512: 2 blocks per (b,c), each handles 1024 rows; partial num/den
// go to scratch, combined in squash.
// ---------------------------------------------------------------------------
__global__ __launch_bounds__(512) void iter_kernel()
{
    const int blk  = blockIdx.x;
    const int bc   = blk >> 1;
    const int half = blk & 1;
    const int t    = threadIdx.x;
    const int o4   = t & 15;            // half4 index over o
    const int g    = t >> 4;            // 0..31 row-lane

    const uint2* p2 = (const uint2*)(g_ph + (size_t)bc * NR * NO)
                      + (size_t)half * 1024 * 16;
    const float4 wv = ((const float4*)g_w)[bc * 16 + o4];

    float d0 = 0.f, d1 = 0.f, d2 = 0.f, d3 = 0.f;
    float n0 = 0.f, n1 = 0.f, n2 = 0.f, n3 = 0.f;

#pragma unroll 8
    for (int k = 0; k < 32; k++) {
        uint2 u = p2[(size_t)(g + 32 * k) * 16 + o4];
        float2 pa = __half22float2(*(__half2*)&u.x);
        float2 pb = __half22float2(*(__half2*)&u.y);
        float e;
        e = __expf(pa.x * wv.x); d0 += e; n0 += pa.x * e;
        e = __expf(pa.y * wv.y); d1 += e; n1 += pa.y * e;
        e = __expf(pb.x * wv.z); d2 += e; n2 += pb.x * e;
        e = __expf(pb.y * wv.w); d3 += e; n3 += pb.y * e;
    }

    __shared__ float sm[2][32][64];     // den / num, 16 KB
    {
        int ob = o4 * 4;
        sm[0][g][ob + 0] = d0; sm[1][g][ob + 0] = n0;
        sm[0][g][ob + 1] = d1; sm[1][g][ob + 1] = n1;
        sm[0][g][ob + 2] = d2; sm[1][g][ob + 2] = n2;
        sm[0][g][ob + 3] = d3; sm[1][g][ob + 3] = n3;
    }
    __syncthreads();

    if (t < 64) {
        float D = 0.f, N = 0.f;
#pragma unroll 8
        for (int g2 = 0; g2 < 32; g2++) {
            D += sm[0][g2][t];
            N += sm[1][g2][t];
        }
        g_pden[half * (NB * NC * NO) + bc * NO + t] = D;
        g_pnum[half * (NB * NC * NO) + bc * NO + t] = N;
    }
}

// ---------------------------------------------------------------------------
// Kernel 3: combine partials -> s, global squash scale, update w or write out.
// Single block, 512 threads, 32 outputs/thread.
// ---------------------------------------------------------------------------
__global__ __launch_bounds__(512) void squash_kernel(float* __restrict__ out, int last)
{
    const int t = threadIdx.x;
    const int TOT = NB * NC * NO;       // 16384

    float sv[32];
    float acc = 0.f;
#pragma unroll
    for (int q = 0; q < 32; q++) {
        int j = t + 512 * q;
        float D = g_pden[j] + g_pden[TOT + j];
        float N = g_pnum[j] + g_pnum[TOT + j];
        float s = N / D;
        sv[q] = s;
        acc += s * s;
    }

    __shared__ float red[16];
    __shared__ float s_scale;
#pragma unroll
    for (int off = 16; off > 0; off >>= 1)
        acc += __shfl_xor_sync(0xFFFFFFFFu, acc, off);
    if ((t & 31) == 0) red[t >> 5] = acc;
    __syncthreads();
    if (t < 32) {
        float a = (t < 16) ? red[t] : 0.f;
#pragma unroll
        for (int off = 8; off > 0; off >>= 1)
            a += __shfl_xor_sync(0xFFFFFFFFu, a, off);
        if (t == 0) s_scale = sqrtf(a) / (1.0f + a);
    }
    __syncthreads();
    const float sc = s_scale;

    if (last) {
#pragma unroll
        for (int q = 0; q < 32; q++) out[t + 512 * q] = sv[q] * sc;
    } else {
#pragma unroll
        for (int q = 0; q < 32; q++) g_w[t + 512 * q] += sv[q] * sc;
    }
}

// ---------------------------------------------------------------------------
extern "C" void kernel_launch(void* const* d_in, const int* in_sizes, int n_in,
                              void* d_out, int out_size)
{
    (void)in_sizes; (void)n_in; (void)out_size;
    const float* x  = (const float*)d_in[0];
    const float* Wt = (const float*)d_in[1];
    float* out = (float*)d_out;

    priors_kernel<<<dim3(NR / 8, NC), 128>>>(x, Wt);

    iter_kernel<<<2 * NB * NC, 512>>>();
    squash_kernel<<<1, 512>>>(nullptr, 0);      // w = v0

    iter_kernel<<<2 * NB * NC, 512>>>();
    squash_kernel<<<1, 512>>>(nullptr, 0);      // w = v0 + v1

    iter_kernel<<<2 * NB * NC, 512>>>();
    squash_kernel<<<1, 512>>>(out, 1);
}